// round 8
// baseline (speedup 1.0000x reference)
#include <cuda_runtime.h>

// FM second-order interaction:
//   out[b] = 0.5 * ( sum_k (x@v)[b,k]^2  -  sum_f x[b,f]^2 * w[f] ),
//   w[f] = sum_k v[f,k]^2
// B=16384, F=2048, K=64, fp32.
//
// fm_main: block = 64 rows x 64 k-cols, F chunked by 32.
//   64 threads, thread tile = 8 rows x 8 cols, accumulators packed f32x2
//   along the ROW axis (row pairs come natively from the transposed x tile;
//   v is stored DUPLICATED in smem so (v,v) pairs load natively too).
//   Inner step: 2 LDS.128 (x) + 4 LDS.128 (v, broadcast) + 32 fma.rn.f32x2.

#define B_ROWS 16384
#define F_DIM  2048
#define K_DIM  64

#define MT      64
#define FC      32
#define THREADS 64

#define XS_ROW  96     // 8 regions * 12 floats (8 rows + 4 pad) -> conflict-free LDS.128
#define VS_ROW  128    // 64 cols duplicated (v,v)

typedef unsigned long long ull;

__device__ float g_w[F_DIM];

// ---------------------------------------------------------------------------
__global__ void fm_prep_w(const float* __restrict__ v) {
    int f = blockIdx.x * blockDim.x + threadIdx.x;
    if (f < F_DIM) {
        const float4* row = reinterpret_cast<const float4*>(v + (size_t)f * K_DIM);
        float s = 0.f;
#pragma unroll
        for (int i = 0; i < K_DIM / 4; i++) {
            float4 a = row[i];
            s += a.x * a.x + a.y * a.y + a.z * a.z + a.w * a.w;
        }
        g_w[f] = s;
    }
}

// ---------------------------------------------------------------------------
__global__ __launch_bounds__(THREADS, 6)
void fm_main(const float* __restrict__ x,
             const float* __restrict__ v,
             float* __restrict__ out) {
    __shared__ float xs[FC * XS_ROW];     // transposed x chunk, region layout
    __shared__ float vs[FC * VS_ROW];     // v chunk, duplicated pairs
    __shared__ float sred[8 * MT];        // k-partial sums across col-groups

    const int tid     = threadIdx.x;
    const int rowBase = blockIdx.x * MT;

    // compute mapping: rg = tid&7 (8 row-groups), cg = tid>>3 (8 col-groups).
    // One 8-lane LDS phase = one cg (v reads broadcast), 8 rgs (x reads
    // hit all 32 banks via 48B region stride).
    const int rg = tid & 7;
    const int cg = tid >> 3;

    // staging mapping: thread stages row r = tid; transposed position:
    const int pos = 12 * (tid >> 3) + (tid & 7);

    ull acc[4][8];                        // [row-pair][col]
#pragma unroll
    for (int i = 0; i < 4; i++)
#pragma unroll
        for (int c = 0; c < 8; c++) acc[i][c] = 0ull;

    float dloc = 0.f;                     // sum_f x[tid,f]^2 * w[f]

    for (int f0 = 0; f0 < F_DIM; f0 += FC) {
        __syncthreads();                  // previous compute done with smem

        // ---- stage x chunk (transposed, region layout) + diag term ----
        {
            const float* xrow = x + (size_t)(rowBase + tid) * F_DIM + f0;
            const float* wrow = g_w + f0;
#pragma unroll
            for (int it = 0; it < FC / 4; it++) {
                float4 a  = *reinterpret_cast<const float4*>(xrow + 4 * it);
                float4 w4 = *reinterpret_cast<const float4*>(wrow + 4 * it);
                dloc += a.x * a.x * w4.x + a.y * a.y * w4.y
                      + a.z * a.z * w4.z + a.w * a.w * w4.w;
                int fl = 4 * it;
                xs[(fl + 0) * XS_ROW + pos] = a.x;
                xs[(fl + 1) * XS_ROW + pos] = a.y;
                xs[(fl + 2) * XS_ROW + pos] = a.z;
                xs[(fl + 3) * XS_ROW + pos] = a.w;
            }
        }

        // ---- stage v chunk, duplicated: vs[fl][2c] = vs[fl][2c+1] = v ----
        {
            const int vfl = tid >> 1;             // 0..31
            const int ofs = (tid & 1) * 32;       // half the 64 cols
            const float* vrow = v + (size_t)(f0 + vfl) * K_DIM + ofs;
            float* dst = &vs[vfl * VS_ROW + 2 * ofs];
#pragma unroll
            for (int it = 0; it < 8; it++) {
                float4 a = *reinterpret_cast<const float4*>(vrow + 4 * it);
                reinterpret_cast<float4*>(dst + 8 * it)[0] =
                    make_float4(a.x, a.x, a.y, a.y);
                reinterpret_cast<float4*>(dst + 8 * it)[1] =
                    make_float4(a.z, a.z, a.w, a.w);
            }
        }
        __syncthreads();

        // ---- compute: FC rank-1 outer-product updates ----
#pragma unroll 4
        for (int fl = 0; fl < FC; fl++) {
            // x: rows 8rg..8rg+7 as 4 packed pairs (2x LDS.128)
            const longlong2* xr =
                reinterpret_cast<const longlong2*>(&xs[fl * XS_ROW + 12 * rg]);
            longlong2 xa = xr[0];
            longlong2 xb = xr[1];
            // v: cols 8cg..8cg+7 duplicated as 8 packed pairs (4x LDS.128, broadcast)
            const longlong2* vr =
                reinterpret_cast<const longlong2*>(&vs[fl * VS_ROW + 16 * cg]);
            longlong2 q0 = vr[0], q1 = vr[1], q2 = vr[2], q3 = vr[3];

            ull xp0 = (ull)xa.x, xp1 = (ull)xa.y, xp2 = (ull)xb.x, xp3 = (ull)xb.y;
            ull vd0 = (ull)q0.x, vd1 = (ull)q0.y, vd2 = (ull)q1.x, vd3 = (ull)q1.y;
            ull vd4 = (ull)q2.x, vd5 = (ull)q2.y, vd6 = (ull)q3.x, vd7 = (ull)q3.y;

#define FMA2(ACC, XP, VV) \
            asm("fma.rn.f32x2 %0, %1, %2, %0;" : "+l"(ACC) : "l"(XP), "l"(VV))

            FMA2(acc[0][0], xp0, vd0); FMA2(acc[0][1], xp0, vd1);
            FMA2(acc[0][2], xp0, vd2); FMA2(acc[0][3], xp0, vd3);
            FMA2(acc[0][4], xp0, vd4); FMA2(acc[0][5], xp0, vd5);
            FMA2(acc[0][6], xp0, vd6); FMA2(acc[0][7], xp0, vd7);
            FMA2(acc[1][0], xp1, vd0); FMA2(acc[1][1], xp1, vd1);
            FMA2(acc[1][2], xp1, vd2); FMA2(acc[1][3], xp1, vd3);
            FMA2(acc[1][4], xp1, vd4); FMA2(acc[1][5], xp1, vd5);
            FMA2(acc[1][6], xp1, vd6); FMA2(acc[1][7], xp1, vd7);
            FMA2(acc[2][0], xp2, vd0); FMA2(acc[2][1], xp2, vd1);
            FMA2(acc[2][2], xp2, vd2); FMA2(acc[2][3], xp2, vd3);
            FMA2(acc[2][4], xp2, vd4); FMA2(acc[2][5], xp2, vd5);
            FMA2(acc[2][6], xp2, vd6); FMA2(acc[2][7], xp2, vd7);
            FMA2(acc[3][0], xp3, vd0); FMA2(acc[3][1], xp3, vd1);
            FMA2(acc[3][2], xp3, vd2); FMA2(acc[3][3], xp3, vd3);
            FMA2(acc[3][4], xp3, vd4); FMA2(acc[3][5], xp3, vd5);
            FMA2(acc[3][6], xp3, vd6); FMA2(acc[3][7], xp3, vd7);
#undef FMA2
        }
    }

    // ---- epilogue: per-row sum of xv^2 over this thread's 8 cols ----
    // acc[rp][c]: lo half -> row 8rg+2rp, hi half -> row 8rg+2rp+1.
#pragma unroll
    for (int rp = 0; rp < 4; rp++) {
        float slo = 0.f, shi = 0.f;
#pragma unroll
        for (int c = 0; c < 8; c++) {
            float lo = __uint_as_float((unsigned)(acc[rp][c] & 0xffffffffull));
            float hi = __uint_as_float((unsigned)(acc[rp][c] >> 32));
            slo += lo * lo;
            shi += hi * hi;
        }
        sred[cg * MT + 8 * rg + 2 * rp + 0] = slo;
        sred[cg * MT + 8 * rg + 2 * rp + 1] = shi;
    }
    __syncthreads();

    // thread tid owns row tid (and its dloc from staging)
    float S = 0.f;
#pragma unroll
    for (int c = 0; c < 8; c++) S += sred[c * MT + tid];
    out[rowBase + tid] = 0.5f * (S - dloc);
}

// ---------------------------------------------------------------------------
extern "C" void kernel_launch(void* const* d_in, const int* in_sizes, int n_in,
                              void* d_out, int out_size) {
    const float* x = (const float*)d_in[0];   // (16384, 2048) fp32
    const float* v = (const float*)d_in[1];   // (2048, 64)    fp32
    float* out = (float*)d_out;               // (16384, 1)    fp32

    fm_prep_w<<<F_DIM / 128, 128>>>(v);
    fm_main<<<B_ROWS / MT, THREADS>>>(x, v, out);
}